// round 4
// baseline (speedup 1.0000x reference)
#include <cuda_runtime.h>
#include <cooperative_groups.h>

namespace cg = cooperative_groups;

#define VOCABN 1000
#define EMBN   128
#define HIDN   256
#define G4N    1024   // 4*HID
#define BN     64
#define TN     1024

#define CL     8      // CTAs per cluster
#define GB     4      // batch rows per cluster
#define NTH    256

// Precomputed per-vocab gate projections: proj[v][g] = emb[v].W_ih[g] + b_ih[g] + b_hh[g]
__device__ float g_proj[VOCABN * G4N];

// ---------------- packed f32x2 helpers ----------------
__device__ __forceinline__ unsigned long long fma2(unsigned long long a,
                                                   unsigned long long b,
                                                   unsigned long long c) {
    unsigned long long d;
    asm("fma.rn.f32x2 %0, %1, %2, %3;" : "=l"(d) : "l"(a), "l"(b), "l"(c));
    return d;
}
__device__ __forceinline__ float lo32(unsigned long long v) {
    return __uint_as_float((unsigned)v);
}
__device__ __forceinline__ float hi32(unsigned long long v) {
    return __uint_as_float((unsigned)(v >> 32));
}

__device__ __forceinline__ float sigf(float x) {
    return __fdividef(1.0f, 1.0f + __expf(-x));
}
__device__ __forceinline__ float tanhf_(float x) {
    return 1.0f - __fdividef(2.0f, __expf(2.0f * x) + 1.0f);
}

// ---------------- mbarrier helpers (cluster scope) ----------------
__device__ __forceinline__ unsigned smem_u32(const void* p) {
    return (unsigned)__cvta_generic_to_shared(p);
}
__device__ __forceinline__ void mbar_init(unsigned a, unsigned cnt) {
    asm volatile("mbarrier.init.shared.b64 [%0], %1;" :: "r"(a), "r"(cnt) : "memory");
}
__device__ __forceinline__ unsigned mapa_u32(unsigned a, unsigned rank) {
    unsigned r;
    asm("mapa.shared::cluster.u32 %0, %1, %2;" : "=r"(r) : "r"(a), "r"(rank));
    return r;
}
__device__ __forceinline__ void mbar_arrive_remote(unsigned remote_addr) {
    asm volatile(
        "mbarrier.arrive.release.cluster.shared::cluster.b64 _, [%0];"
        :: "r"(remote_addr) : "memory");
}
__device__ __forceinline__ void mbar_wait_acq_cluster(unsigned a, unsigned parity) {
    asm volatile(
        "{\n\t"
        ".reg .pred P;\n\t"
        "WLOOP_%=:\n\t"
        "mbarrier.try_wait.parity.acquire.cluster.shared::cta.b64 P, [%0], %1, 0x989680;\n\t"
        "@P bra.uni WDONE_%=;\n\t"
        "bra.uni WLOOP_%=;\n\t"
        "WDONE_%=:\n\t"
        "}"
        :: "r"(a), "r"(parity) : "memory");
}
__device__ __forceinline__ void cluster_sync_once() {
    asm volatile("barrier.cluster.arrive.aligned;" ::: "memory");
    asm volatile("barrier.cluster.wait.aligned;" ::: "memory");
}

// ---------------------------------------------------------------------------
// Kernel 1: vocab projection table. 125 blocks x 256 threads, 8 vocab/block.
// ---------------------------------------------------------------------------
__global__ void __launch_bounds__(256) proj_kernel(
    const float* __restrict__ emb, const float* __restrict__ W_ih,
    const float* __restrict__ b_ih, const float* __restrict__ b_hh)
{
    __shared__ float4 es4[8][EMBN / 4];
    const int v0 = blockIdx.x * 8;
    const int tid = threadIdx.x;
    for (int i = tid; i < 8 * EMBN; i += 256) {
        int v = i >> 7, e = i & 127;
        ((float*)es4)[v * EMBN + e] = emb[(v0 + v) * EMBN + e];
    }
    __syncthreads();

    const float4* W4 = (const float4*)W_ih;
#pragma unroll
    for (int rr = 0; rr < 4; rr++) {
        int g = tid + rr * 256;
        float acc[8];
#pragma unroll
        for (int v = 0; v < 8; v++) acc[v] = 0.f;
        for (int e4 = 0; e4 < EMBN / 4; e4++) {
            float4 w = W4[g * (EMBN / 4) + e4];
#pragma unroll
            for (int v = 0; v < 8; v++) {
                float4 x = es4[v][e4];
                acc[v] += w.x * x.x + w.y * x.y + w.z * x.z + w.w * x.w;
            }
        }
        float bias = b_ih[g] + b_hh[g];
#pragma unroll
        for (int v = 0; v < 8; v++)
            g_proj[(v0 + v) * G4N + g] = acc[v] + bias;
    }
}

// ---------------------------------------------------------------------------
// Kernel 2: recurrence. 16 clusters x 8 CTAs; each cluster owns 4 batch rows.
// CTA rank r owns h indices [r*32, r*32+32) => 128 W_hh gate rows, held in
// registers (128 floats = 64 f32x2 pairs per thread, k-half split).
// Per step: matvec -> psum STS -> one __syncthreads -> paired-lane cell with
// shfl gate exchange -> DSMEM push -> __syncthreads -> 8 remote mbarrier
// arrives. Consumers spin on a local mbarrier (acquire.cluster) — no
// cluster.sync, no L1 flush, single-hop arrival.
// ---------------------------------------------------------------------------
__global__ void __launch_bounds__(NTH, 1) __cluster_dims__(CL, 1, 1)
lstm_kernel(const int* __restrict__ tokens, const int* __restrict__ lengths,
            const float* __restrict__ W_hh, float* __restrict__ out)
{
    __shared__ float hb[2][GB][HIDN];        // 8 KB: double-buffered h, batch-major
    __shared__ float psum[GB][128][2];       // 4 KB: [batch][gate-row][k-half]
    __shared__ __align__(8) unsigned long long mbar[2];

    cg::cluster_group cluster = cg::this_cluster();
    const int rank = blockIdx.x;              // 0..7
    const int cid  = blockIdx.y;              // 0..15
    const int tid  = threadIdx.x;
    const int lr   = tid & 127;               // gate row 0..127
    const int hf   = tid >> 7;                // k-half 0/1
    const int base = rank * 32;
    const int grow = (lr >> 5) * HIDN + base + (lr & 31);
    const int b0   = cid * GB;

    // W_hh slice into registers: 128 floats (k-half of one gate row) = 64 pairs
    unsigned long long wpair[64];
    {
        const ulonglong2* wr =
            (const ulonglong2*)(W_hh + (size_t)grow * HIDN + hf * 128);
#pragma unroll
        for (int j = 0; j < 32; j++) {
            ulonglong2 v = wr[j];
            wpair[2 * j]     = v.x;
            wpair[2 * j + 1] = v.y;
        }
    }

    if (tid == 0) {
        mbar_init(smem_u32(&mbar[0]), CL);
        mbar_init(smem_u32(&mbar[1]), CL);
    }
    for (int i = tid; i < GB * HIDN; i += NTH) ((float*)hb[0])[i] = 0.f;
    __syncthreads();
    cluster_sync_once();   // mbarrier init + hb zero visible cluster-wide

    // cell identity: lane pairs (2j, 2j+1) share one (h,batch) pair
    const int pr = tid >> 1;        // 0..127
    const int s  = tid & 1;         // gate-split: 0 -> {i,f}, 1 -> {g,o}
    const int hl = pr & 31;
    const int bb = pr >> 5;
    const int mylen = lengths[b0 + bb];

    const int len0 = lengths[b0 + 0];
    const int len1 = lengths[b0 + 1];
    const int len2 = lengths[b0 + 2];
    const int len3 = lengths[b0 + 3];
    int steps = max(max(len0, len1), max(len2, len3));
    if (steps > TN) steps = TN;

    // input projections (rows = tid<128 hold them)
    float xw0 = 0.f, xw1 = 0.f, xw2 = 0.f, xw3 = 0.f;
    if (hf == 0) {
        xw0 = g_proj[tokens[(b0 + 0) * TN] * G4N + grow];
        xw1 = g_proj[tokens[(b0 + 1) * TN] * G4N + grow];
        xw2 = g_proj[tokens[(b0 + 2) * TN] * G4N + grow];
        xw3 = g_proj[tokens[(b0 + 3) * TN] * G4N + grow];
    }

    float creg = 0.f, hreg = 0.f;
    unsigned ph0 = 0, ph1 = 0;   // phase parity per mbarrier
    const unsigned mb0 = smem_u32(&mbar[0]);
    const unsigned mb1 = smem_u32(&mbar[1]);

    for (int t = 0; t < steps; t++) {
        // wait for h(t) from all 8 producers (skip t=0: h0 = 0 prezeroed)
        if (t) {
            if (t & 1) { mbar_wait_acq_cluster(mb1, ph1); if (tid == 0) {} ph1 ^= 1; }
            else       { mbar_wait_acq_cluster(mb0, ph0); ph0 ^= 1; }
        }

        // prefetch next step's input projection (L2 latency hidden by matvec)
        float xn0, xn1, xn2, xn3;
        if (hf == 0) {
            int tn = min(t + 1, TN - 1);
            xn0 = g_proj[tokens[(b0 + 0) * TN + tn] * G4N + grow];
            xn1 = g_proj[tokens[(b0 + 1) * TN + tn] * G4N + grow];
            xn2 = g_proj[tokens[(b0 + 2) * TN + tn] * G4N + grow];
            xn3 = g_proj[tokens[(b0 + 3) * TN + tn] * G4N + grow];
        }

        // packed matvec: this thread's gate row, its k-half, 4 batches
        const float* h0p = hb[t & 1][0] + hf * 128;
        const float* h1p = hb[t & 1][1] + hf * 128;
        const float* h2p = hb[t & 1][2] + hf * 128;
        const float* h3p = hb[t & 1][3] + hf * 128;
        unsigned long long a0 = 0ull, a1 = 0ull, a2 = 0ull, a3 = 0ull;
#pragma unroll 8
        for (int c = 0; c < 32; c++) {
            ulonglong2 h0 = *(const ulonglong2*)(h0p + c * 4);
            ulonglong2 h1 = *(const ulonglong2*)(h1p + c * 4);
            ulonglong2 h2 = *(const ulonglong2*)(h2p + c * 4);
            ulonglong2 h3 = *(const ulonglong2*)(h3p + c * 4);
            a0 = fma2(wpair[2 * c], h0.x, a0);
            a1 = fma2(wpair[2 * c], h1.x, a1);
            a2 = fma2(wpair[2 * c], h2.x, a2);
            a3 = fma2(wpair[2 * c], h3.x, a3);
            a0 = fma2(wpair[2 * c + 1], h0.y, a0);
            a1 = fma2(wpair[2 * c + 1], h1.y, a1);
            a2 = fma2(wpair[2 * c + 1], h2.y, a2);
            a3 = fma2(wpair[2 * c + 1], h3.y, a3);
        }
        // scalar partials (pair-summed); k-half 0 folds in the input projection
        if (hf == 0) {
            psum[0][lr][0] = lo32(a0) + hi32(a0) + xw0;
            psum[1][lr][0] = lo32(a1) + hi32(a1) + xw1;
            psum[2][lr][0] = lo32(a2) + hi32(a2) + xw2;
            psum[3][lr][0] = lo32(a3) + hi32(a3) + xw3;
            xw0 = xn0; xw1 = xn1; xw2 = xn2; xw3 = xn3;
        } else {
            psum[0][lr][1] = lo32(a0) + hi32(a0);
            psum[1][lr][1] = lo32(a1) + hi32(a1);
            psum[2][lr][1] = lo32(a2) + hi32(a2);
            psum[3][lr][1] = lo32(a3) + hi32(a3);
        }
        __syncthreads();

        // cell update: lane pair (s=0: sig(i),sig(f); s=1: tanh(g),sig(o))
        {
            const int r0 = (s ? 64 : 0) + hl;
            const int r1 = (s ? 96 : 32) + hl;
            float gA = psum[bb][r0][0] + psum[bb][r0][1];
            float gB = psum[bb][r1][0] + psum[bb][r1][1];
            float u = s ? tanhf_(gA) : sigf(gA);
            float v = sigf(gB);
            float ou = __shfl_xor_sync(0xffffffffu, u, 1);
            float ov = __shfl_xor_sync(0xffffffffu, v, 1);
            float i_ = s ? ou : u;
            float f_ = s ? ov : v;
            float g_ = s ? u  : ou;
            float o_ = s ? v  : ov;
            float cn = f_ * creg + i_ * g_;
            float hn = o_ * tanhf_(cn);
            if (t < mylen) { creg = cn; hreg = hn; }
        }

        if (t + 1 < steps) {
            // push my (h,b) value to 4 of the 8 CTAs (pair lane covers the rest)
            float* dst = &hb[(t & 1) ^ 1][bb][base + hl];
#pragma unroll
            for (int r = 0; r < 4; r++) {
                float* p = (float*)cluster.map_shared_rank(dst, 4 * s + r);
                *p = hreg;
            }
            __syncthreads();   // all pushes issued before the release-arrives
            if (tid < CL) {
                unsigned local_mb = ((t + 1) & 1) ? mb1 : mb0;
                mbar_arrive_remote(mapa_u32(local_mb, tid));
            }
        }
    }

    if (s == 0)
        out[(b0 + bb) * HIDN + base + hl] = hreg;
}

// ---------------------------------------------------------------------------
extern "C" void kernel_launch(void* const* d_in, const int* in_sizes, int n_in,
                              void* d_out, int out_size)
{
    const int*   tokens  = (const int*)d_in[0];
    const int*   lengths = (const int*)d_in[1];
    const float* emb     = (const float*)d_in[2];
    const float* W_ih    = (const float*)d_in[3];
    const float* W_hh    = (const float*)d_in[4];
    const float* b_ih    = (const float*)d_in[5];
    const float* b_hh    = (const float*)d_in[6];
    float* out = (float*)d_out;

    proj_kernel<<<VOCABN / 8, 256>>>(emb, W_ih, b_ih, b_hh);

    dim3 grid(CL, BN / GB);
    lstm_kernel<<<grid, NTH>>>(tokens, lengths, W_hh, out);
}

// round 5
// speedup vs baseline: 1.8958x; 1.8958x over previous
#include <cuda_runtime.h>

#define VOCABN 1000
#define EMBN   128
#define HIDN   256
#define G4N    1024   // 4*HID
#define BN     64
#define TN     1024

#define CL     8      // CTAs per cluster
#define GB     4      // batch rows per cluster
#define NTH    256

// Precomputed per-vocab gate projections: proj[v][g] = emb[v].W_ih[g] + b_ih[g] + b_hh[g]
__device__ float g_proj[VOCABN * G4N];

// ---------------- packed f32x2 helpers ----------------
__device__ __forceinline__ unsigned long long fma2(unsigned long long a,
                                                   unsigned long long b,
                                                   unsigned long long c) {
    unsigned long long d;
    asm("fma.rn.f32x2 %0, %1, %2, %3;" : "=l"(d) : "l"(a), "l"(b), "l"(c));
    return d;
}
__device__ __forceinline__ float lo32(unsigned long long v) {
    return __uint_as_float((unsigned)v);
}
__device__ __forceinline__ float hi32(unsigned long long v) {
    return __uint_as_float((unsigned)(v >> 32));
}

__device__ __forceinline__ float sigf(float x) {
    return __fdividef(1.0f, 1.0f + __expf(-x));
}
__device__ __forceinline__ float tanhf_(float x) {
    return 1.0f - __fdividef(2.0f, __expf(2.0f * x) + 1.0f);
}

// ---------------- cluster smem / mbarrier helpers ----------------
__device__ __forceinline__ unsigned smem_u32(const void* p) {
    return (unsigned)__cvta_generic_to_shared(p);
}
__device__ __forceinline__ void mbar_init(unsigned a, unsigned cnt) {
    asm volatile("mbarrier.init.shared.b64 [%0], %1;" :: "r"(a), "r"(cnt) : "memory");
}
__device__ __forceinline__ unsigned mapa_u32(unsigned a, unsigned rank) {
    unsigned r;
    asm("mapa.shared::cluster.u32 %0, %1, %2;" : "=r"(r) : "r"(a), "r"(rank));
    return r;
}
__device__ __forceinline__ void mbar_arm(unsigned a, unsigned tx_bytes) {
    asm volatile("mbarrier.arrive.expect_tx.shared.b64 _, [%0], %1;"
                 :: "r"(a), "r"(tx_bytes) : "memory");
}
// remote store, counts bytes into the destination CTA's mbarrier
__device__ __forceinline__ void st_async_f32(unsigned dst, float v, unsigned mb) {
    asm volatile(
        "st.async.shared::cluster.mbarrier::complete_tx::bytes.b32 [%0], %1, [%2];"
        :: "r"(dst), "r"(__float_as_uint(v)), "r"(mb) : "memory");
}
__device__ __forceinline__ void mbar_wait(unsigned a, unsigned parity) {
    asm volatile(
        "{\n\t"
        ".reg .pred P;\n\t"
        "mbarrier.try_wait.parity.acquire.cluster.shared::cta.b64 P, [%0], %1;\n\t"
        "@P bra.uni WDONE_%=;\n\t"
        "WLOOP_%=:\n\t"
        "mbarrier.try_wait.parity.acquire.cluster.shared::cta.b64 P, [%0], %1, 0x989680;\n\t"
        "@!P bra.uni WLOOP_%=;\n\t"
        "WDONE_%=:\n\t"
        "}"
        :: "r"(a), "r"(parity) : "memory");
}
__device__ __forceinline__ void cluster_sync_once() {
    asm volatile("barrier.cluster.arrive.aligned;" ::: "memory");
    asm volatile("barrier.cluster.wait.aligned;" ::: "memory");
}

// ---------------------------------------------------------------------------
// Kernel 1: vocab projection table. 125 blocks x 256 threads, 8 vocab/block.
// ---------------------------------------------------------------------------
__global__ void __launch_bounds__(256) proj_kernel(
    const float* __restrict__ emb, const float* __restrict__ W_ih,
    const float* __restrict__ b_ih, const float* __restrict__ b_hh)
{
    __shared__ float4 es4[8][EMBN / 4];
    const int v0 = blockIdx.x * 8;
    const int tid = threadIdx.x;
    for (int i = tid; i < 8 * EMBN; i += 256) {
        int v = i >> 7, e = i & 127;
        ((float*)es4)[v * EMBN + e] = emb[(v0 + v) * EMBN + e];
    }
    __syncthreads();

    const float4* W4 = (const float4*)W_ih;
#pragma unroll
    for (int rr = 0; rr < 4; rr++) {
        int g = tid + rr * 256;
        float acc[8];
#pragma unroll
        for (int v = 0; v < 8; v++) acc[v] = 0.f;
        for (int e4 = 0; e4 < EMBN / 4; e4++) {
            float4 w = W4[g * (EMBN / 4) + e4];
#pragma unroll
            for (int v = 0; v < 8; v++) {
                float4 x = es4[v][e4];
                acc[v] += w.x * x.x + w.y * x.y + w.z * x.z + w.w * x.w;
            }
        }
        float bias = b_ih[g] + b_hh[g];
#pragma unroll
        for (int v = 0; v < 8; v++)
            g_proj[(v0 + v) * G4N + g] = acc[v] + bias;
    }
}

// ---------------------------------------------------------------------------
// Kernel 2: recurrence. 16 clusters x 8 CTAs; each cluster owns 4 batch rows.
// CTA rank r owns h indices [r*32, r*32+32) => 128 W_hh gate rows in registers.
// h exchange: st.async remote stores carrying mbarrier complete_tx — the
// consumer's try_wait IS the sync; no cluster.sync, no release-membar.
// Barriers are double-buffered and re-armed immediately after each wait,
// which globally precedes any push that could target the re-armed phase.
// ---------------------------------------------------------------------------
__global__ void __launch_bounds__(NTH, 1) __cluster_dims__(CL, 1, 1)
lstm_kernel(const int* __restrict__ tokens, const int* __restrict__ lengths,
            const float* __restrict__ W_hh, float* __restrict__ out)
{
    __shared__ float hb[2][GB][HIDN];          // 8 KB: double-buffered h, batch-major
    __shared__ float psum[GB][2][128];         // 4 KB: [batch][k-half][gate-row]
    __shared__ __align__(8) unsigned long long mbar[2];

    const int rank = blockIdx.x;               // 0..7
    const int cid  = blockIdx.y;               // 0..15
    const int tid  = threadIdx.x;
    const int lr   = tid & 127;                // gate row 0..127
    const int hf   = tid >> 7;                 // k-half 0/1
    const int base = rank * 32;
    const int grow = (lr >> 5) * HIDN + base + (lr & 31);
    const int b0   = cid * GB;
    const unsigned TXB = 4096;                 // bytes per exchange phase

    // W_hh slice into registers: 128 floats (k-half of one gate row) = 64 pairs
    unsigned long long wpair[64];
    {
        const ulonglong2* wr =
            (const ulonglong2*)(W_hh + (size_t)grow * HIDN + hf * 128);
#pragma unroll
        for (int j = 0; j < 32; j++) {
            ulonglong2 v = wr[j];
            wpair[2 * j]     = v.x;
            wpair[2 * j + 1] = v.y;
        }
    }

    const unsigned mb0 = smem_u32(&mbar[0]);
    const unsigned mb1 = smem_u32(&mbar[1]);
    if (tid == 0) {
        mbar_init(mb0, 1);
        mbar_init(mb1, 1);
        mbar_arm(mb1, TXB);    // pre-arm for t=1 data (arrives into hb[1])
    }
    for (int i = tid; i < GB * HIDN; i += NTH) ((float*)hb[0])[i] = 0.f;
    __syncthreads();
    cluster_sync_once();       // init + hb[0]=0 visible cluster-wide before any push

    // cell identity: lane pairs (2j, 2j+1) share one (h,batch); s splits gates
    const int pr = tid >> 1;        // 0..127
    const int s  = tid & 1;         // 0 -> {i,f}, 1 -> {g,o}
    const int hl = pr & 31;
    const int bb = pr >> 5;
    const int mylen = lengths[b0 + bb];

    const int len0 = lengths[b0 + 0];
    const int len1 = lengths[b0 + 1];
    const int len2 = lengths[b0 + 2];
    const int len3 = lengths[b0 + 3];
    int steps = max(max(len0, len1), max(len2, len3));
    if (steps > TN) steps = TN;

    float xw0 = 0.f, xw1 = 0.f, xw2 = 0.f, xw3 = 0.f;
    if (hf == 0) {
        xw0 = g_proj[tokens[(b0 + 0) * TN] * G4N + grow];
        xw1 = g_proj[tokens[(b0 + 1) * TN] * G4N + grow];
        xw2 = g_proj[tokens[(b0 + 2) * TN] * G4N + grow];
        xw3 = g_proj[tokens[(b0 + 3) * TN] * G4N + grow];
    }

    float creg = 0.f, hreg = 0.f;
    unsigned ph0 = 0, ph1 = 0;

    for (int t = 0; t < steps; t++) {
        const int buf = t & 1;
        // wait for h(t) (skip t=0: hb[0] prezeroed), then immediately re-arm
        // this barrier for the phase two steps ahead.
        if (t) {
            if (buf) { mbar_wait(mb1, ph1); ph1 ^= 1; }
            else     { mbar_wait(mb0, ph0); ph0 ^= 1; }
        }
        if (tid == 0) mbar_arm(buf ? mb1 : mb0, TXB);

        // prefetch next step's input projection (L2 latency hidden by matvec)
        float xn0, xn1, xn2, xn3;
        if (hf == 0) {
            int tn = min(t + 1, TN - 1);
            xn0 = g_proj[tokens[(b0 + 0) * TN + tn] * G4N + grow];
            xn1 = g_proj[tokens[(b0 + 1) * TN + tn] * G4N + grow];
            xn2 = g_proj[tokens[(b0 + 2) * TN + tn] * G4N + grow];
            xn3 = g_proj[tokens[(b0 + 3) * TN + tn] * G4N + grow];
        }

        // packed matvec: this thread's gate row, its k-half, 4 batches
        const float* h0p = hb[buf][0] + hf * 128;
        const float* h1p = hb[buf][1] + hf * 128;
        const float* h2p = hb[buf][2] + hf * 128;
        const float* h3p = hb[buf][3] + hf * 128;
        unsigned long long a0 = 0ull, a1 = 0ull, a2 = 0ull, a3 = 0ull;
#pragma unroll 8
        for (int c = 0; c < 32; c++) {
            ulonglong2 h0 = *(const ulonglong2*)(h0p + c * 4);
            ulonglong2 h1 = *(const ulonglong2*)(h1p + c * 4);
            ulonglong2 h2 = *(const ulonglong2*)(h2p + c * 4);
            ulonglong2 h3 = *(const ulonglong2*)(h3p + c * 4);
            a0 = fma2(wpair[2 * c], h0.x, a0);
            a1 = fma2(wpair[2 * c], h1.x, a1);
            a2 = fma2(wpair[2 * c], h2.x, a2);
            a3 = fma2(wpair[2 * c], h3.x, a3);
            a0 = fma2(wpair[2 * c + 1], h0.y, a0);
            a1 = fma2(wpair[2 * c + 1], h1.y, a1);
            a2 = fma2(wpair[2 * c + 1], h2.y, a2);
            a3 = fma2(wpair[2 * c + 1], h3.y, a3);
        }
        if (hf == 0) {
            psum[0][0][lr] = lo32(a0) + hi32(a0) + xw0;
            psum[1][0][lr] = lo32(a1) + hi32(a1) + xw1;
            psum[2][0][lr] = lo32(a2) + hi32(a2) + xw2;
            psum[3][0][lr] = lo32(a3) + hi32(a3) + xw3;
            xw0 = xn0; xw1 = xn1; xw2 = xn2; xw3 = xn3;
        } else {
            psum[0][1][lr] = lo32(a0) + hi32(a0);
            psum[1][1][lr] = lo32(a1) + hi32(a1);
            psum[2][1][lr] = lo32(a2) + hi32(a2);
            psum[3][1][lr] = lo32(a3) + hi32(a3);
        }
        __syncthreads();

        // cell update: lane pair (s=0: sig(i),sig(f); s=1: tanh(g),sig(o))
        {
            const int r0 = (s ? 64 : 0) + hl;
            const int r1 = (s ? 96 : 32) + hl;
            float gA = psum[bb][0][r0] + psum[bb][1][r0];
            float gB = psum[bb][0][r1] + psum[bb][1][r1];
            float u = s ? tanhf_(gA) : sigf(gA);
            float v = sigf(gB);
            float ou = __shfl_xor_sync(0xffffffffu, u, 1);
            float ov = __shfl_xor_sync(0xffffffffu, v, 1);
            float i_ = s ? ou : u;
            float f_ = s ? ov : v;
            float g_ = s ? u  : ou;
            float o_ = s ? v  : ov;
            float cn = f_ * creg + i_ * g_;
            float hn = o_ * tanhf_(cn);
            if (t < mylen) { creg = cn; hreg = hn; }
        }

        if (t + 1 < steps) {
            // fire-and-forget: remote stores carry their own completion signal
            const int nb = buf ^ 1;
            const unsigned dloc = smem_u32(&hb[nb][bb][base + hl]);
            const unsigned mloc = nb ? mb1 : mb0;
#pragma unroll
            for (int r = 0; r < 4; r++) {
                const unsigned rk = 4 * s + r;
                st_async_f32(mapa_u32(dloc, rk), hreg, mapa_u32(mloc, rk));
            }
        }
    }

    if (s == 0)
        out[(b0 + bb) * HIDN + base + hl] = hreg;
}

// ---------------------------------------------------------------------------
extern "C" void kernel_launch(void* const* d_in, const int* in_sizes, int n_in,
                              void* d_out, int out_size)
{
    const int*   tokens  = (const int*)d_in[0];
    const int*   lengths = (const int*)d_in[1];
    const float* emb     = (const float*)d_in[2];
    const float* W_ih    = (const float*)d_in[3];
    const float* W_hh    = (const float*)d_in[4];
    const float* b_ih    = (const float*)d_in[5];
    const float* b_hh    = (const float*)d_in[6];
    float* out = (float*)d_out;

    proj_kernel<<<VOCABN / 8, 256>>>(emb, W_ih, b_ih, b_hh);

    dim3 grid(CL, BN / GB);
    lstm_kernel<<<grid, NTH>>>(tokens, lengths, W_hh, out);
}

// round 6
// speedup vs baseline: 1.9566x; 1.0321x over previous
#include <cuda_runtime.h>

#define VOCABN 1000
#define EMBN   128
#define HIDN   256
#define G4N    1024   // 4*HID
#define BN     64
#define TN     1024

#define CL     8      // CTAs per cluster
#define GB     4      // batch rows per cluster
#define NTH    256

// Precomputed per-vocab gate projections: proj[v][g] = emb[v].W_ih[g] + b_ih[g] + b_hh[g]
__device__ float g_proj[VOCABN * G4N];

// ---------------- packed f32x2 helpers ----------------
__device__ __forceinline__ unsigned long long fma2(unsigned long long a,
                                                   unsigned long long b,
                                                   unsigned long long c) {
    unsigned long long d;
    asm("fma.rn.f32x2 %0, %1, %2, %3;" : "=l"(d) : "l"(a), "l"(b), "l"(c));
    return d;
}
__device__ __forceinline__ float lo32(unsigned long long v) {
    return __uint_as_float((unsigned)v);
}
__device__ __forceinline__ float hi32(unsigned long long v) {
    return __uint_as_float((unsigned)(v >> 32));
}

__device__ __forceinline__ float sigf(float x) {
    return __fdividef(1.0f, 1.0f + __expf(-x));
}
__device__ __forceinline__ float tanhf_(float x) {
    return 1.0f - __fdividef(2.0f, __expf(2.0f * x) + 1.0f);
}

// ---------------- cluster smem / mbarrier helpers ----------------
__device__ __forceinline__ unsigned smem_u32(const void* p) {
    return (unsigned)__cvta_generic_to_shared(p);
}
__device__ __forceinline__ void mbar_init(unsigned a, unsigned cnt) {
    asm volatile("mbarrier.init.shared.b64 [%0], %1;" :: "r"(a), "r"(cnt) : "memory");
}
__device__ __forceinline__ unsigned mapa_u32(unsigned a, unsigned rank) {
    unsigned r;
    asm("mapa.shared::cluster.u32 %0, %1, %2;" : "=r"(r) : "r"(a), "r"(rank));
    return r;
}
__device__ __forceinline__ void mbar_arm(unsigned a, unsigned tx_bytes) {
    asm volatile("mbarrier.arrive.expect_tx.shared.b64 _, [%0], %1;"
                 :: "r"(a), "r"(tx_bytes) : "memory");
}
// remote store, counts bytes into the destination CTA's mbarrier
__device__ __forceinline__ void st_async_f32(unsigned dst, float v, unsigned mb) {
    asm volatile(
        "st.async.shared::cluster.mbarrier::complete_tx::bytes.b32 [%0], %1, [%2];"
        :: "r"(dst), "r"(__float_as_uint(v)), "r"(mb) : "memory");
}
__device__ __forceinline__ void mbar_wait(unsigned a, unsigned parity) {
    asm volatile(
        "{\n\t"
        ".reg .pred P;\n\t"
        "mbarrier.try_wait.parity.acquire.cluster.shared::cta.b64 P, [%0], %1;\n\t"
        "@P bra.uni WDONE_%=;\n\t"
        "WLOOP_%=:\n\t"
        "mbarrier.try_wait.parity.acquire.cluster.shared::cta.b64 P, [%0], %1, 0x989680;\n\t"
        "@!P bra.uni WLOOP_%=;\n\t"
        "WDONE_%=:\n\t"
        "}"
        :: "r"(a), "r"(parity) : "memory");
}
__device__ __forceinline__ void cluster_sync_once() {
    asm volatile("barrier.cluster.arrive.aligned;" ::: "memory");
    asm volatile("barrier.cluster.wait.aligned;" ::: "memory");
}

// ---------------------------------------------------------------------------
// Kernel 1: vocab projection table. 125 blocks x 256 threads, 8 vocab/block.
// ---------------------------------------------------------------------------
__global__ void __launch_bounds__(256) proj_kernel(
    const float* __restrict__ emb, const float* __restrict__ W_ih,
    const float* __restrict__ b_ih, const float* __restrict__ b_hh)
{
    __shared__ float4 es4[8][EMBN / 4];
    const int v0 = blockIdx.x * 8;
    const int tid = threadIdx.x;
    for (int i = tid; i < 8 * EMBN; i += 256) {
        int v = i >> 7, e = i & 127;
        ((float*)es4)[v * EMBN + e] = emb[(v0 + v) * EMBN + e];
    }
    __syncthreads();

    const float4* W4 = (const float4*)W_ih;
#pragma unroll
    for (int rr = 0; rr < 4; rr++) {
        int g = tid + rr * 256;
        float acc[8];
#pragma unroll
        for (int v = 0; v < 8; v++) acc[v] = 0.f;
        for (int e4 = 0; e4 < EMBN / 4; e4++) {
            float4 w = W4[g * (EMBN / 4) + e4];
#pragma unroll
            for (int v = 0; v < 8; v++) {
                float4 x = es4[v][e4];
                acc[v] += w.x * x.x + w.y * x.y + w.z * x.z + w.w * x.w;
            }
        }
        float bias = b_ih[g] + b_hh[g];
#pragma unroll
        for (int v = 0; v < 8; v++)
            g_proj[(v0 + v) * G4N + g] = acc[v] + bias;
    }
}

// ---------------------------------------------------------------------------
// Kernel 2: recurrence. 16 clusters x 8 CTAs; cluster owns 4 batch rows.
// CTA rank r owns h indices [r*32, r*32+32) => 128 W_hh gate rows, held in
// SMEM in pair-transposed layout Wp2[cp][row] (cp = group of 4 k-floats as
// ulonglong2): a warp's 32 lanes read 32 consecutive 16B elements ->
// conflict-free LDS.128, and NO register spills (W never touches the RF
// persistently). h exchange stays st.async + double-buffered mbarriers.
// ---------------------------------------------------------------------------
__global__ void __launch_bounds__(NTH, 1) __cluster_dims__(CL, 1, 1)
lstm_kernel(const int* __restrict__ tokens, const int* __restrict__ lengths,
            const float* __restrict__ W_hh, float* __restrict__ out)
{
    extern __shared__ __align__(16) char smraw[];
    ulonglong2* Wp2  = (ulonglong2*)smraw;                    // [64][128] 128 KB
    float (*hb)[GB][HIDN] = (float (*)[GB][HIDN])(smraw + 131072);  // [2][4][256] 8 KB
    float (*psum)[2][128] = (float (*)[2][128])(smraw + 131072 + 8192); // [4][2][128] 4 KB
    unsigned long long* mbar = (unsigned long long*)(smraw + 131072 + 8192 + 4096);

    const int rank = blockIdx.x;               // 0..7
    const int cid  = blockIdx.y;               // 0..15
    const int tid  = threadIdx.x;
    const int lr   = tid & 127;                // gate row 0..127
    const int hf   = tid >> 7;                 // k-half 0/1
    const int base = rank * 32;
    const int b0   = cid * GB;
    const unsigned TXB = 4096;                 // bytes per exchange phase
    const int grow = (lr >> 5) * HIDN + base + (lr & 31);  // my W_hh row

    // --- load W slice into SMEM, pair-transposed: Wp2[cp*128 + row] ---
    // row-major over (row, cp) for coalesced gmem reads.
    for (int i = tid; i < 128 * 64; i += NTH) {
        int row = i >> 6, cp = i & 63;
        int gr = ((row >> 5) * HIDN) + base + (row & 31);
        Wp2[cp * 128 + row] = ((const ulonglong2*)(W_hh + (size_t)gr * HIDN))[cp];
    }

    const unsigned mb0 = smem_u32(&mbar[0]);
    const unsigned mb1 = smem_u32(&mbar[1]);
    if (tid == 0) {
        mbar_init(mb0, 1);
        mbar_init(mb1, 1);
        mbar_arm(mb1, TXB);    // pre-arm for t=1 data (arrives into hb[1])
    }
    for (int i = tid; i < GB * HIDN; i += NTH) ((float*)hb[0])[i] = 0.f;
    __syncthreads();
    cluster_sync_once();       // init + hb[0]=0 visible cluster-wide before any push

    // cell identity: lane pairs (2j, 2j+1) share one (h,batch); s splits gates
    const int pr = tid >> 1;        // 0..127
    const int s  = tid & 1;         // 0 -> {i,f}, 1 -> {g,o}
    const int hl = pr & 31;
    const int bb = pr >> 5;
    const int mylen = lengths[b0 + bb];

    const int len0 = lengths[b0 + 0];
    const int len1 = lengths[b0 + 1];
    const int len2 = lengths[b0 + 2];
    const int len3 = lengths[b0 + 3];
    int steps = max(max(len0, len1), max(len2, len3));
    if (steps > TN) steps = TN;

    float xw0 = 0.f, xw1 = 0.f, xw2 = 0.f, xw3 = 0.f;
    if (hf == 0) {
        xw0 = g_proj[tokens[(b0 + 0) * TN] * G4N + grow];
        xw1 = g_proj[tokens[(b0 + 1) * TN] * G4N + grow];
        xw2 = g_proj[tokens[(b0 + 2) * TN] * G4N + grow];
        xw3 = g_proj[tokens[(b0 + 3) * TN] * G4N + grow];
    }

    float creg = 0.f, hreg = 0.f;
    unsigned ph0 = 0, ph1 = 0;
    const ulonglong2* wbase = Wp2 + (hf * 32) * 128 + lr;   // step 128 per cp

    for (int t = 0; t < steps; t++) {
        const int buf = t & 1;
        // wait for h(t) (skip t=0: hb[0] prezeroed), then re-arm this barrier
        // for the phase two steps ahead.
        if (t) {
            if (buf) { mbar_wait(mb1, ph1); ph1 ^= 1; }
            else     { mbar_wait(mb0, ph0); ph0 ^= 1; }
        }
        if (tid == 0) mbar_arm(buf ? mb1 : mb0, TXB);

        // prefetch next step's input projection (L2 latency hidden by matvec)
        float xn0, xn1, xn2, xn3;
        if (hf == 0) {
            int tn = min(t + 1, TN - 1);
            xn0 = g_proj[tokens[(b0 + 0) * TN + tn] * G4N + grow];
            xn1 = g_proj[tokens[(b0 + 1) * TN + tn] * G4N + grow];
            xn2 = g_proj[tokens[(b0 + 2) * TN + tn] * G4N + grow];
            xn3 = g_proj[tokens[(b0 + 3) * TN + tn] * G4N + grow];
        }

        // packed matvec: this thread's gate row, its k-half, 4 batches.
        // W from SMEM (conflict-free LDS.128), h from SMEM (broadcast LDS.128).
        const float* h0p = hb[buf][0] + hf * 128;
        const float* h1p = hb[buf][1] + hf * 128;
        const float* h2p = hb[buf][2] + hf * 128;
        const float* h3p = hb[buf][3] + hf * 128;
        unsigned long long a0 = 0ull, a1 = 0ull, a2 = 0ull, a3 = 0ull;
#pragma unroll 8
        for (int c = 0; c < 32; c++) {
            ulonglong2 w  = wbase[c * 128];
            ulonglong2 h0 = *(const ulonglong2*)(h0p + c * 4);
            ulonglong2 h1 = *(const ulonglong2*)(h1p + c * 4);
            ulonglong2 h2 = *(const ulonglong2*)(h2p + c * 4);
            ulonglong2 h3 = *(const ulonglong2*)(h3p + c * 4);
            a0 = fma2(w.x, h0.x, a0);
            a1 = fma2(w.x, h1.x, a1);
            a2 = fma2(w.x, h2.x, a2);
            a3 = fma2(w.x, h3.x, a3);
            a0 = fma2(w.y, h0.y, a0);
            a1 = fma2(w.y, h1.y, a1);
            a2 = fma2(w.y, h2.y, a2);
            a3 = fma2(w.y, h3.y, a3);
        }
        if (hf == 0) {
            psum[0][0][lr] = lo32(a0) + hi32(a0) + xw0;
            psum[1][0][lr] = lo32(a1) + hi32(a1) + xw1;
            psum[2][0][lr] = lo32(a2) + hi32(a2) + xw2;
            psum[3][0][lr] = lo32(a3) + hi32(a3) + xw3;
            xw0 = xn0; xw1 = xn1; xw2 = xn2; xw3 = xn3;
        } else {
            psum[0][1][lr] = lo32(a0) + hi32(a0);
            psum[1][1][lr] = lo32(a1) + hi32(a1);
            psum[2][1][lr] = lo32(a2) + hi32(a2);
            psum[3][1][lr] = lo32(a3) + hi32(a3);
        }
        __syncthreads();

        // cell update: lane pair (s=0: sig(i),sig(f); s=1: tanh(g),sig(o))
        {
            const int r0 = (s ? 64 : 0) + hl;
            const int r1 = (s ? 96 : 32) + hl;
            float gA = psum[bb][0][r0] + psum[bb][1][r0];
            float gB = psum[bb][0][r1] + psum[bb][1][r1];
            float u = s ? tanhf_(gA) : sigf(gA);
            float v = sigf(gB);
            float ou = __shfl_xor_sync(0xffffffffu, u, 1);
            float ov = __shfl_xor_sync(0xffffffffu, v, 1);
            float i_ = s ? ou : u;
            float f_ = s ? ov : v;
            float g_ = s ? u  : ou;
            float o_ = s ? v  : ov;
            float cn = f_ * creg + i_ * g_;
            float hn = o_ * tanhf_(cn);
            if (t < mylen) { creg = cn; hreg = hn; }
        }

        if (t + 1 < steps) {
            // fire-and-forget: remote stores carry their own completion signal
            const int nb = buf ^ 1;
            const unsigned dloc = smem_u32(&hb[nb][bb][base + hl]);
            const unsigned mloc = nb ? mb1 : mb0;
#pragma unroll
            for (int r = 0; r < 4; r++) {
                const unsigned rk = 4 * s + r;
                st_async_f32(mapa_u32(dloc, rk), hreg, mapa_u32(mloc, rk));
            }
        }
    }

    if (s == 0)
        out[(b0 + bb) * HIDN + base + hl] = hreg;
}

// ---------------------------------------------------------------------------
extern "C" void kernel_launch(void* const* d_in, const int* in_sizes, int n_in,
                              void* d_out, int out_size)
{
    const int*   tokens  = (const int*)d_in[0];
    const int*   lengths = (const int*)d_in[1];
    const float* emb     = (const float*)d_in[2];
    const float* W_ih    = (const float*)d_in[3];
    const float* W_hh    = (const float*)d_in[4];
    const float* b_ih    = (const float*)d_in[5];
    const float* b_hh    = (const float*)d_in[6];
    float* out = (float*)d_out;

    proj_kernel<<<VOCABN / 8, 256>>>(emb, W_ih, b_ih, b_hh);

    const int smem_bytes = 131072 + 8192 + 4096 + 16;   // Wp2 + hb + psum + mbar
    cudaFuncSetAttribute(lstm_kernel,
                         cudaFuncAttributeMaxDynamicSharedMemorySize, smem_bytes);
    dim3 grid(CL, BN / GB);
    lstm_kernel<<<grid, NTH, smem_bytes>>>(tokens, lengths, W_hh, out);
}

// round 7
// speedup vs baseline: 2.3655x; 1.2090x over previous
#include <cuda_runtime.h>

#define VOCABN 1000
#define EMBN   128
#define HIDN   256
#define G4N    1024   // 4*HID
#define BN     64
#define TN     1024

#define CL     8      // CTAs per cluster
#define GB     4      // batch rows per cluster
#define NTH    512    // 128 gate rows x 4 k-quarters

// Precomputed per-vocab gate projections: proj[v][g] = emb[v].W_ih[g] + b_ih[g] + b_hh[g]
__device__ float g_proj[VOCABN * G4N];

// ---------------- packed f32x2 helpers ----------------
__device__ __forceinline__ unsigned long long fma2(unsigned long long a,
                                                   unsigned long long b,
                                                   unsigned long long c) {
    unsigned long long d;
    asm("fma.rn.f32x2 %0, %1, %2, %3;" : "=l"(d) : "l"(a), "l"(b), "l"(c));
    return d;
}
__device__ __forceinline__ float lo32(unsigned long long v) {
    return __uint_as_float((unsigned)v);
}
__device__ __forceinline__ float hi32(unsigned long long v) {
    return __uint_as_float((unsigned)(v >> 32));
}

__device__ __forceinline__ float sigf(float x) {
    return __fdividef(1.0f, 1.0f + __expf(-x));
}
__device__ __forceinline__ float tanhf_(float x) {
    return 1.0f - __fdividef(2.0f, __expf(2.0f * x) + 1.0f);
}

// ---------------- cluster smem / mbarrier helpers ----------------
__device__ __forceinline__ unsigned smem_u32(const void* p) {
    return (unsigned)__cvta_generic_to_shared(p);
}
__device__ __forceinline__ void mbar_init(unsigned a, unsigned cnt) {
    asm volatile("mbarrier.init.shared.b64 [%0], %1;" :: "r"(a), "r"(cnt) : "memory");
}
__device__ __forceinline__ unsigned mapa_u32(unsigned a, unsigned rank) {
    unsigned r;
    asm("mapa.shared::cluster.u32 %0, %1, %2;" : "=r"(r) : "r"(a), "r"(rank));
    return r;
}
__device__ __forceinline__ void mbar_arm(unsigned a, unsigned tx_bytes) {
    asm volatile("mbarrier.arrive.expect_tx.shared.b64 _, [%0], %1;"
                 :: "r"(a), "r"(tx_bytes) : "memory");
}
// remote store, counts bytes into the destination CTA's mbarrier
__device__ __forceinline__ void st_async_f32(unsigned dst, float v, unsigned mb) {
    asm volatile(
        "st.async.shared::cluster.mbarrier::complete_tx::bytes.b32 [%0], %1, [%2];"
        :: "r"(dst), "r"(__float_as_uint(v)), "r"(mb) : "memory");
}
__device__ __forceinline__ void mbar_wait(unsigned a, unsigned parity) {
    asm volatile(
        "{\n\t"
        ".reg .pred P;\n\t"
        "mbarrier.try_wait.parity.acquire.cluster.shared::cta.b64 P, [%0], %1;\n\t"
        "@P bra.uni WDONE_%=;\n\t"
        "WLOOP_%=:\n\t"
        "mbarrier.try_wait.parity.acquire.cluster.shared::cta.b64 P, [%0], %1, 0x989680;\n\t"
        "@!P bra.uni WLOOP_%=;\n\t"
        "WDONE_%=:\n\t"
        "}"
        :: "r"(a), "r"(parity) : "memory");
}
__device__ __forceinline__ void cluster_sync_once() {
    asm volatile("barrier.cluster.arrive.aligned;" ::: "memory");
    asm volatile("barrier.cluster.wait.aligned;" ::: "memory");
}

// ---------------------------------------------------------------------------
// Kernel 1: vocab projection table. 125 blocks x 256 threads, 8 vocab/block.
// ---------------------------------------------------------------------------
__global__ void __launch_bounds__(256) proj_kernel(
    const float* __restrict__ emb, const float* __restrict__ W_ih,
    const float* __restrict__ b_ih, const float* __restrict__ b_hh)
{
    __shared__ float4 es4[8][EMBN / 4];
    const int v0 = blockIdx.x * 8;
    const int tid = threadIdx.x;
    for (int i = tid; i < 8 * EMBN; i += 256) {
        int v = i >> 7, e = i & 127;
        ((float*)es4)[v * EMBN + e] = emb[(v0 + v) * EMBN + e];
    }
    __syncthreads();

    const float4* W4 = (const float4*)W_ih;
#pragma unroll
    for (int rr = 0; rr < 4; rr++) {
        int g = tid + rr * 256;
        float acc[8];
#pragma unroll
        for (int v = 0; v < 8; v++) acc[v] = 0.f;
        for (int e4 = 0; e4 < EMBN / 4; e4++) {
            float4 w = W4[g * (EMBN / 4) + e4];
#pragma unroll
            for (int v = 0; v < 8; v++) {
                float4 x = es4[v][e4];
                acc[v] += w.x * x.x + w.y * x.y + w.z * x.z + w.w * x.w;
            }
        }
        float bias = b_ih[g] + b_hh[g];
#pragma unroll
        for (int v = 0; v < 8; v++)
            g_proj[(v0 + v) * G4N + g] = acc[v] + bias;
    }
}

// ---------------------------------------------------------------------------
// Kernel 2: recurrence. 16 clusters x 8 CTAs; cluster owns 4 batch rows.
// Thread = (gate row lr in 0..127, k-quarter q in 0..3). Each thread keeps
// its 64 W_hh floats in 32 u64 registers (k-quarter of one gate row) —
// zero per-step W traffic. All per-step LDS are warp-uniform h broadcasts.
// psum[4 quarters] reduced by the cell threads inside the single barrier.
// h exchange: st.async remote stores + double-buffered tx mbarriers.
// ---------------------------------------------------------------------------
__global__ void __launch_bounds__(NTH, 1) __cluster_dims__(CL, 1, 1)
lstm_kernel(const int* __restrict__ tokens, const int* __restrict__ lengths,
            const float* __restrict__ W_hh, float* __restrict__ out)
{
    __shared__ float hb[2][GB][HIDN];          // 8 KB: double-buffered h, batch-major
    __shared__ float psum[4][GB][128];         // 8 KB: [quarter][batch][gate-row]
    __shared__ __align__(8) unsigned long long mbar[2];

    const int rank = blockIdx.x;               // 0..7
    const int cid  = blockIdx.y;               // 0..15
    const int tid  = threadIdx.x;
    const int lr   = tid & 127;                // gate row 0..127
    const int q    = tid >> 7;                 // k-quarter 0..3
    const int base = rank * 32;
    const int b0   = cid * GB;
    const unsigned TXB = 4096;                 // bytes per exchange phase
    const int grow = (lr >> 5) * HIDN + base + (lr & 31);  // my W_hh row

    // --- W slice into registers: 64 floats (k-quarter of a row) = 32 pairs ---
    unsigned long long wpair[32];
    {
        const ulonglong2* wr =
            (const ulonglong2*)(W_hh + (size_t)grow * HIDN + q * 64);
#pragma unroll
        for (int j = 0; j < 16; j++) {
            ulonglong2 v = wr[j];
            wpair[2 * j]     = v.x;
            wpair[2 * j + 1] = v.y;
        }
    }

    const unsigned mb0 = smem_u32(&mbar[0]);
    const unsigned mb1 = smem_u32(&mbar[1]);
    if (tid == 0) {
        mbar_init(mb0, 1);
        mbar_init(mb1, 1);
        mbar_arm(mb1, TXB);    // pre-arm for t=1 data (arrives into hb[1])
    }
    for (int i = tid; i < GB * HIDN; i += NTH) ((float*)hb[0])[i] = 0.f;
    __syncthreads();
    cluster_sync_once();       // init + hb[0]=0 visible cluster-wide before any push

    // cell identity (tid<256): lane pairs (2j,2j+1) share one (h,batch)
    const int pr = tid >> 1;        // 0..127 (for tid<256)
    const int s  = tid & 1;         // 0 -> {i,f}, 1 -> {g,o}
    const int hl = pr & 31;
    const int bb = pr >> 5;
    const int mylen = (tid < 256) ? lengths[b0 + bb] : 0;

    const int len0 = lengths[b0 + 0];
    const int len1 = lengths[b0 + 1];
    const int len2 = lengths[b0 + 2];
    const int len3 = lengths[b0 + 3];
    int steps = max(max(len0, len1), max(len2, len3));
    if (steps > TN) steps = TN;

    // input projections live in the q==0 threads (tid<128, one per gate row)
    float xw0 = 0.f, xw1 = 0.f, xw2 = 0.f, xw3 = 0.f;
    if (q == 0) {
        xw0 = g_proj[tokens[(b0 + 0) * TN] * G4N + grow];
        xw1 = g_proj[tokens[(b0 + 1) * TN] * G4N + grow];
        xw2 = g_proj[tokens[(b0 + 2) * TN] * G4N + grow];
        xw3 = g_proj[tokens[(b0 + 3) * TN] * G4N + grow];
    }

    float creg = 0.f, hreg = 0.f;
    unsigned ph0 = 0, ph1 = 0;

    for (int t = 0; t < steps; t++) {
        const int buf = t & 1;
        // wait for h(t) (skip t=0: hb[0] prezeroed), then re-arm this barrier
        // for the phase two steps ahead.
        if (t) {
            if (buf) { mbar_wait(mb1, ph1); ph1 ^= 1; }
            else     { mbar_wait(mb0, ph0); ph0 ^= 1; }
        }
        if (tid == 0) mbar_arm(buf ? mb1 : mb0, TXB);

        // prefetch next step's input projection (L2 latency hidden by matvec)
        float xn0, xn1, xn2, xn3;
        if (q == 0) {
            int tn = min(t + 1, TN - 1);
            xn0 = g_proj[tokens[(b0 + 0) * TN + tn] * G4N + grow];
            xn1 = g_proj[tokens[(b0 + 1) * TN + tn] * G4N + grow];
            xn2 = g_proj[tokens[(b0 + 2) * TN + tn] * G4N + grow];
            xn3 = g_proj[tokens[(b0 + 3) * TN + tn] * G4N + grow];
        }

        // packed matvec: my gate row, my k-quarter, 4 batches.
        // W from registers; h via warp-uniform broadcast LDS.128.
        const float* h0p = hb[buf][0] + q * 64;
        const float* h1p = hb[buf][1] + q * 64;
        const float* h2p = hb[buf][2] + q * 64;
        const float* h3p = hb[buf][3] + q * 64;
        unsigned long long a0 = 0ull, a1 = 0ull, a2 = 0ull, a3 = 0ull;
#pragma unroll
        for (int c = 0; c < 16; c++) {
            ulonglong2 h0 = *(const ulonglong2*)(h0p + c * 4);
            ulonglong2 h1 = *(const ulonglong2*)(h1p + c * 4);
            ulonglong2 h2 = *(const ulonglong2*)(h2p + c * 4);
            ulonglong2 h3 = *(const ulonglong2*)(h3p + c * 4);
            a0 = fma2(wpair[2 * c], h0.x, a0);
            a1 = fma2(wpair[2 * c], h1.x, a1);
            a2 = fma2(wpair[2 * c], h2.x, a2);
            a3 = fma2(wpair[2 * c], h3.x, a3);
            a0 = fma2(wpair[2 * c + 1], h0.y, a0);
            a1 = fma2(wpair[2 * c + 1], h1.y, a1);
            a2 = fma2(wpair[2 * c + 1], h2.y, a2);
            a3 = fma2(wpair[2 * c + 1], h3.y, a3);
        }
        // pair-summed scalar partials; quarter 0 folds in the input projection
        if (q == 0) {
            psum[0][0][lr] = lo32(a0) + hi32(a0) + xw0;
            psum[0][1][lr] = lo32(a1) + hi32(a1) + xw1;
            psum[0][2][lr] = lo32(a2) + hi32(a2) + xw2;
            psum[0][3][lr] = lo32(a3) + hi32(a3) + xw3;
            xw0 = xn0; xw1 = xn1; xw2 = xn2; xw3 = xn3;
        } else {
            psum[q][0][lr] = lo32(a0) + hi32(a0);
            psum[q][1][lr] = lo32(a1) + hi32(a1);
            psum[q][2][lr] = lo32(a2) + hi32(a2);
            psum[q][3][lr] = lo32(a3) + hi32(a3);
        }
        __syncthreads();

        // cell update on tid<256: lane pair (s=0: sig(i),sig(f); s=1: tanh(g),sig(o))
        if (tid < 256) {
            const int r0 = (s ? 64 : 0) + hl;
            const int r1 = (s ? 96 : 32) + hl;
            float gA = (psum[0][bb][r0] + psum[1][bb][r0]) +
                       (psum[2][bb][r0] + psum[3][bb][r0]);
            float gB = (psum[0][bb][r1] + psum[1][bb][r1]) +
                       (psum[2][bb][r1] + psum[3][bb][r1]);
            float u = s ? tanhf_(gA) : sigf(gA);
            float v = sigf(gB);
            float ou = __shfl_xor_sync(0xffffffffu, u, 1);
            float ov = __shfl_xor_sync(0xffffffffu, v, 1);
            float i_ = s ? ou : u;
            float f_ = s ? ov : v;
            float g_ = s ? u  : ou;
            float o_ = s ? v  : ov;
            float cn = f_ * creg + i_ * g_;
            float hn = o_ * tanhf_(cn);
            if (t < mylen) { creg = cn; hreg = hn; }

            if (t + 1 < steps) {
                // fire-and-forget: remote stores carry their own completion
                const int nb = buf ^ 1;
                const unsigned dloc = smem_u32(&hb[nb][bb][base + hl]);
                const unsigned mloc = nb ? mb1 : mb0;
#pragma unroll
                for (int r = 0; r < 4; r++) {
                    const unsigned rk = 4 * s + r;
                    st_async_f32(mapa_u32(dloc, rk), hreg, mapa_u32(mloc, rk));
                }
            }
        }
    }

    if (tid < 256 && s == 0)
        out[(b0 + bb) * HIDN + base + hl] = hreg;
}

// ---------------------------------------------------------------------------
extern "C" void kernel_launch(void* const* d_in, const int* in_sizes, int n_in,
                              void* d_out, int out_size)
{
    const int*   tokens  = (const int*)d_in[0];
    const int*   lengths = (const int*)d_in[1];
    const float* emb     = (const float*)d_in[2];
    const float* W_ih    = (const float*)d_in[3];
    const float* W_hh    = (const float*)d_in[4];
    const float* b_ih    = (const float*)d_in[5];
    const float* b_hh    = (const float*)d_in[6];
    float* out = (float*)d_out;

    proj_kernel<<<VOCABN / 8, 256>>>(emb, W_ih, b_ih, b_hh);

    dim3 grid(CL, BN / GB);
    lstm_kernel<<<grid, NTH>>>(tokens, lengths, W_hh, out);
}